// round 3
// baseline (speedup 1.0000x reference)
#include <cuda_runtime.h>
#include <math_constants.h>

// ---------------------------------------------------------------------------
// SC_Att_Bridge: 5-level spatial attention (CBAM-style), fp32.
// Phase 1: per-pixel channel mean+max  -> g_avg/g_max (float4, ILP-2)
// Phase 2: dilated 7x7 conv (d=3,p=9) + bias + sigmoid -> g_att
// Phase 3: out = t * (1 + att)  (float4, ILP-2)
// ---------------------------------------------------------------------------

#define NTOT_PIX 698368   // sum over tensors of N*H*W (N=8)

__device__ float g_avg[NTOT_PIX];
__device__ float g_max[NTOT_PIX];
__device__ float g_att[NTOT_PIX];

// shapes: (8,64,256,256)(8,128,128,128)(8,256,64,64)(8,512,32,32)(8,512,16,16)
__constant__ int c_C[5]       = {64, 128, 256, 512, 512};
__constant__ int c_HW[5]      = {65536, 16384, 4096, 1024, 256};
__constant__ int c_lgHW[5]    = {16, 14, 12, 10, 8};
__constant__ int c_W[5]       = {256, 128, 64, 32, 16};
__constant__ int c_poff[5]    = {0, 524288, 655360, 688128, 696320};          // pixel offsets
__constant__ int c_eoff[5]    = {0, 33554432, 50331648, 58720256, 62914560};  // element offsets
__constant__ int c_lgCHW[5]   = {22, 21, 20, 19, 17};
__constant__ int c_redcum[5]  = {0, 2048, 2560, 2688, 2720};   // reduce blocks (256 px each)
__constant__ int c_convcum[5] = {0, 2048, 2560, 2688, 2720};   // conv blocks
__constant__ int c_tpn[5]     = {256, 64, 16, 4, 1};           // 16x16 tiles per image
__constant__ int c_tilesX[5]  = {16, 8, 4, 2, 1};

// ---------------------------------------------------------------------------
// Phase 1: channel mean + max, float4 x 2 per thread (ILP-2 for MLP).
// Block = 256 threads = 32 lanes x 8 channel-groups; each lane owns two
// float4 pixel chunks 128 apart. Block covers 256 pixels. Grid = 2728.
// Each loop iteration issues 2 independent LDG.128 -> 8 loads in flight
// at unroll 4.
// ---------------------------------------------------------------------------
__global__ __launch_bounds__(256) void reduce_kernel(
    const float* __restrict__ t0, const float* __restrict__ t1,
    const float* __restrict__ t2, const float* __restrict__ t3,
    const float* __restrict__ t4)
{
    __shared__ float4 ss0[256];
    __shared__ float4 ss1[256];
    __shared__ float4 sm0[256];
    __shared__ float4 sm1[256];

    int b = blockIdx.x;
    int i = 0;
    if (b >= 2048) i = 1;
    if (b >= 2560) i = 2;
    if (b >= 2688) i = 3;
    if (b >= 2720) i = 4;

    const float* srcs[5] = {t0, t1, t2, t3, t4};
    const float* __restrict__ src = srcs[i];

    const int tid   = threadIdx.x;
    const int lane  = tid & 31;
    const int grp   = tid >> 5;
    const int base  = (b - c_redcum[i]) << 8;      // 256 pixels per block
    const int pixel = base + (lane << 2);          // chunk0; chunk1 = pixel + 128

    const int HW   = c_HW[i];
    const int C    = c_C[i];
    const int n    = pixel >> c_lgHW[i];           // same n for both chunks (HW>=256, base%256==0)
    const int hw   = pixel & (HW - 1);
    const int HW4  = HW >> 2;

    const float4* __restrict__ p =
        reinterpret_cast<const float4*>(src + (size_t)n * C * HW + hw);

    float4 s0 = make_float4(0.f, 0.f, 0.f, 0.f);
    float4 s1 = make_float4(0.f, 0.f, 0.f, 0.f);
    float4 m0 = make_float4(-CUDART_INF_F, -CUDART_INF_F, -CUDART_INF_F, -CUDART_INF_F);
    float4 m1 = m0;

#pragma unroll 4
    for (int c = grp; c < C; c += 8) {
        const float4* q = p + (size_t)c * HW4;
        float4 v0 = __ldg(q);
        float4 v1 = __ldg(q + 32);                 // +128 pixels
        s0.x += v0.x; s0.y += v0.y; s0.z += v0.z; s0.w += v0.w;
        s1.x += v1.x; s1.y += v1.y; s1.z += v1.z; s1.w += v1.w;
        m0.x = fmaxf(m0.x, v0.x); m0.y = fmaxf(m0.y, v0.y);
        m0.z = fmaxf(m0.z, v0.z); m0.w = fmaxf(m0.w, v0.w);
        m1.x = fmaxf(m1.x, v1.x); m1.y = fmaxf(m1.y, v1.y);
        m1.z = fmaxf(m1.z, v1.z); m1.w = fmaxf(m1.w, v1.w);
    }
    ss0[tid] = s0; ss1[tid] = s1;
    sm0[tid] = m0; sm1[tid] = m1;
    __syncthreads();

    if (tid < 32) {
#pragma unroll
        for (int g = 1; g < 8; g++) {
            float4 a0 = ss0[g * 32 + tid], a1 = ss1[g * 32 + tid];
            float4 b0 = sm0[g * 32 + tid], b1 = sm1[g * 32 + tid];
            s0.x += a0.x; s0.y += a0.y; s0.z += a0.z; s0.w += a0.w;
            s1.x += a1.x; s1.y += a1.y; s1.z += a1.z; s1.w += a1.w;
            m0.x = fmaxf(m0.x, b0.x); m0.y = fmaxf(m0.y, b0.y);
            m0.z = fmaxf(m0.z, b0.z); m0.w = fmaxf(m0.w, b0.w);
            m1.x = fmaxf(m1.x, b1.x); m1.y = fmaxf(m1.y, b1.y);
            m1.z = fmaxf(m1.z, b1.z); m1.w = fmaxf(m1.w, b1.w);
        }
        const float inv = 1.0f / (float)C;
        s0.x *= inv; s0.y *= inv; s0.z *= inv; s0.w *= inv;
        s1.x *= inv; s1.y *= inv; s1.z *= inv; s1.w *= inv;
        const int q4 = (c_poff[i] + pixel) >> 2;   // %4==0
        float4* av = reinterpret_cast<float4*>(g_avg);
        float4* mx = reinterpret_cast<float4*>(g_max);
        av[q4]      = s0;  av[q4 + 32] = s1;
        mx[q4]      = m0;  mx[q4 + 32] = m1;
    }
}

// ---------------------------------------------------------------------------
// Phase 2: dilated 7x7 conv (dilation 3, zero pad 9) over [avg,max], + bias,
// sigmoid. Block = 16x16 output tile; SMEM holds 34x34 halo of both maps.
// Grid = 2728. lax.conv is cross-correlation (no kernel flip).
// ---------------------------------------------------------------------------
__global__ __launch_bounds__(256) void conv_kernel(
    const float* __restrict__ cw, const float* __restrict__ cb)
{
    __shared__ float s_av[34 * 34];
    __shared__ float s_mx[34 * 34];
    __shared__ float s_w[98];

    int b = blockIdx.x;
    int i = 0;
    if (b >= 2048) i = 1;
    if (b >= 2560) i = 2;
    if (b >= 2688) i = 3;
    if (b >= 2720) i = 4;

    const int r      = b - c_convcum[i];
    const int tpn    = c_tpn[i];
    const int n      = r / tpn;
    const int tl     = r - n * tpn;
    const int tilesX = c_tilesX[i];
    const int ty0    = (tl / tilesX) << 4;
    const int tx0    = (tl % tilesX) << 4;
    const int Wd     = c_W[i];
    const int po     = c_poff[i] + (n << c_lgHW[i]);

    const int tid = threadIdx.x;
    if (tid < 98) s_w[tid] = cw[tid];

    for (int idx = tid; idx < 34 * 34; idx += 256) {
        int yy = idx / 34;
        int xx = idx - yy * 34;
        int h  = ty0 + yy - 9;
        int w  = tx0 + xx - 9;
        float a = 0.0f, m = 0.0f;
        if ((unsigned)h < (unsigned)Wd && (unsigned)w < (unsigned)Wd) { // H==W
            int q = po + h * Wd + w;
            a = g_avg[q];
            m = g_max[q];
        }
        s_av[idx] = a;
        s_mx[idx] = m;
    }
    __syncthreads();

    const int ty = tid >> 4;
    const int tx = tid & 15;

    float acc = cb[0];
#pragma unroll
    for (int kh = 0; kh < 7; kh++) {
#pragma unroll
        for (int kw = 0; kw < 7; kw++) {
            int s = (ty + kh * 3) * 34 + (tx + kw * 3);
            acc = fmaf(s_av[s], s_w[kh * 7 + kw],      acc);
            acc = fmaf(s_mx[s], s_w[49 + kh * 7 + kw], acc);
        }
    }
    float att = 1.0f / (1.0f + expf(-acc));
    g_att[po + (ty0 + ty) * Wd + (tx0 + tx)] = att;
}

// ---------------------------------------------------------------------------
// Phase 3: out = t * (1 + att). float4, ILP-2: each thread processes two
// float4 chunks 1024 elements apart. Block covers 2048 elements; every
// tensor boundary is %2048==0, so the segment branch is block-uniform.
// Grid = 31232 blocks exactly.
// ---------------------------------------------------------------------------
__global__ __launch_bounds__(256) void gate_kernel(
    const float* __restrict__ t0, const float* __restrict__ t1,
    const float* __restrict__ t2, const float* __restrict__ t3,
    const float* __restrict__ t4, float* __restrict__ out)
{
    const int tid = threadIdx.x;
    const int e0  = blockIdx.x * 2048 + (tid << 2);
    const int e1  = e0 + 1024;

    int i = 0;
    if (e0 >= 33554432) i = 1;
    if (e0 >= 50331648) i = 2;
    if (e0 >= 58720256) i = 3;
    if (e0 >= 62914560) i = 4;

    const float* srcs[5] = {t0, t1, t2, t3, t4};
    const float* __restrict__ src = srcs[i];

    const int eoff  = c_eoff[i];
    const int lgCHW = c_lgCHW[i];
    const int HWm1  = c_HW[i] - 1;
    const int lgHW  = c_lgHW[i];
    const int poff  = c_poff[i];

    const int l0 = e0 - eoff;
    const int l1 = e1 - eoff;
    const int p0 = poff + ((l0 >> lgCHW) << lgHW) + (l0 & HWm1);
    const int p1 = poff + ((l1 >> lgCHW) << lgHW) + (l1 & HWm1);

    const float4 a0 = *reinterpret_cast<const float4*>(&g_att[p0]);
    const float4 a1 = *reinterpret_cast<const float4*>(&g_att[p1]);
    const float4 v0 = *reinterpret_cast<const float4*>(&src[l0]);
    const float4 v1 = *reinterpret_cast<const float4*>(&src[l1]);

    float4 o0, o1;
    o0.x = fmaf(v0.x, a0.x, v0.x);
    o0.y = fmaf(v0.y, a0.y, v0.y);
    o0.z = fmaf(v0.z, a0.z, v0.z);
    o0.w = fmaf(v0.w, a0.w, v0.w);
    o1.x = fmaf(v1.x, a1.x, v1.x);
    o1.y = fmaf(v1.y, a1.y, v1.y);
    o1.z = fmaf(v1.z, a1.z, v1.z);
    o1.w = fmaf(v1.w, a1.w, v1.w);

    *reinterpret_cast<float4*>(&out[e0]) = o0;
    *reinterpret_cast<float4*>(&out[e1]) = o1;
}

// ---------------------------------------------------------------------------
extern "C" void kernel_launch(void* const* d_in, const int* in_sizes, int n_in,
                              void* d_out, int out_size)
{
    const float* t0 = (const float*)d_in[0];
    const float* t1 = (const float*)d_in[1];
    const float* t2 = (const float*)d_in[2];
    const float* t3 = (const float*)d_in[3];
    const float* t4 = (const float*)d_in[4];
    const float* cw = (const float*)d_in[5];
    const float* cb = (const float*)d_in[6];
    float* out = (float*)d_out;

    reduce_kernel<<<2728, 256>>>(t0, t1, t2, t3, t4);
    conv_kernel<<<2728, 256>>>(cw, cb);
    gate_kernel<<<31232, 256>>>(t0, t1, t2, t3, t4, out);
}